// round 1
// baseline (speedup 1.0000x reference)
#include <cuda_runtime.h>
#include <math.h>

// ---------------------------------------------------------------------------
// Problem constants
//   B=256, NOISE=100, RANK=512, R4=128, R2=256
//   latent (B,256); c (B,512,3); h1 (B,128,16); h2 (B,256,31); h3 (B,512,32)
// ---------------------------------------------------------------------------

__device__ float g_latent[256 * 256];
__device__ float g_c [256 * 512 * 3];
__device__ float g_h1[256 * 128 * 16];
__device__ float g_w1[256 * 128 * 16];
__device__ float g_h2[256 * 256 * 31];
__device__ float g_w2[256 * 256 * 31];
__device__ float g_h3[256 * 512 * 32];
__device__ float g_w3[256 * 512 * 32];

// Block-wide (256 threads) reduction of (sum, sumsq).
__device__ __forceinline__ void reduce2_256(float& s, float& ss) {
    __shared__ float rs[8], rss[8];
    #pragma unroll
    for (int o = 16; o > 0; o >>= 1) {
        s  += __shfl_down_sync(0xffffffffu, s,  o);
        ss += __shfl_down_sync(0xffffffffu, ss, o);
    }
    int wid = threadIdx.x >> 5, lane = threadIdx.x & 31;
    if (lane == 0) { rs[wid] = s; rss[wid] = ss; }
    __syncthreads();
    if (threadIdx.x < 32) {
        float a  = lane < 8 ? rs[lane]  : 0.f;
        float b  = lane < 8 ? rss[lane] : 0.f;
        #pragma unroll
        for (int o = 4; o > 0; o >>= 1) {
            a += __shfl_down_sync(0xffffffffu, a, o);
            b += __shfl_down_sync(0xffffffffu, b, o);
        }
        if (lane == 0) { rs[0] = a; rss[0] = b; }
    }
    __syncthreads();
    s = rs[0]; ss = rss[0];
}

// ---------------------------------------------------------------------------
// Stage 1: z = lrelu(BN(noise @ lin_w.T + lin_b), 0.01); latent = [z, emb[label]]
// grid = 256 blocks: blocks [0,128) compute z channel j (BN over batch),
//                    blocks [128,256) scatter embedding channel j-128.
// ---------------------------------------------------------------------------
__global__ void k_latent(const float* __restrict__ noise, const int* __restrict__ label,
                         const float* __restrict__ lin_w, const float* __restrict__ lin_b,
                         const float* __restrict__ g,     const float* __restrict__ be,
                         const float* __restrict__ emb) {
    int j = blockIdx.x, b = threadIdx.x;
    if (j >= 128) {
        int jj = j - 128;
        g_latent[b * 256 + 128 + jj] = emb[label[b] * 128 + jj];
        return;
    }
    __shared__ float wsm[100];
    if (b < 100) wsm[b] = lin_w[j * 100 + b];
    __syncthreads();
    float acc = lin_b[j];
    const float* nb = noise + b * 100;
    #pragma unroll 4
    for (int i = 0; i < 100; i++) acc += nb[i] * wsm[i];
    float s = acc, ss = acc * acc;
    reduce2_256(s, ss);
    float mean = s * (1.f / 256.f);
    float var  = ss * (1.f / 256.f) - mean * mean;
    float sc   = g[j] * rsqrtf(var + 1e-5f);
    float v    = (acc - mean) * sc + be[j];
    g_latent[b * 256 + j] = v >= 0.f ? v : 0.01f * v;
}

// ---------------------------------------------------------------------------
// Stage 2: first convT on L=1 input == outer product GEMM, fused BN + lrelu.
// W: (256, Cout, K) torch layout. One block per output channel co; thread = b.
// BN statistics over 256*K values — in-block reduce.
// ---------------------------------------------------------------------------
template<int K>
__global__ void k_conv1(const float* __restrict__ W,  const float* __restrict__ bias,
                        const float* __restrict__ g,  const float* __restrict__ be,
                        float* __restrict__ out, int Cout, float slope) {
    int co = blockIdx.x, b = threadIdx.x;
    extern __shared__ float ws[];                 // 256*K
    for (int i = b; i < 256 * K; i += 256)
        ws[i] = W[(i / K) * Cout * K + co * K + (i % K)];
    __syncthreads();
    float acc[K];
    float bv = bias[co];
    #pragma unroll
    for (int t = 0; t < K; t++) acc[t] = bv;
    const float* lat = g_latent + b * 256;
    for (int ci = 0; ci < 256; ci++) {
        float x = lat[ci];
        #pragma unroll
        for (int t = 0; t < K; t++) acc[t] += x * ws[ci * K + t];
    }
    float s = 0.f, ss = 0.f;
    #pragma unroll
    for (int t = 0; t < K; t++) { s += acc[t]; ss += acc[t] * acc[t]; }
    reduce2_256(s, ss);
    const float invN = 1.f / (256.f * (float)K);
    float mean = s * invN, var = ss * invN - mean * mean;
    float sc = g[co] * rsqrtf(var + 1e-5f);
    float sh = be[co] - mean * sc;
    #pragma unroll
    for (int t = 0; t < K; t++) {
        float v = acc[t] * sc + sh;
        out[(b * Cout + co) * K + t] = v >= 0.f ? v : slope * v;
    }
}

// ---------------------------------------------------------------------------
// Stage 3: convT k=16: (B,128,16) -> (B,256,31), fused BN + lrelu(0.2).
// W: (128, 256, 16). One block per co (256 blocks); thread = b.
// ---------------------------------------------------------------------------
__global__ void k_convT16(const float* __restrict__ in, const float* __restrict__ W,
                          const float* __restrict__ bias, const float* __restrict__ g,
                          const float* __restrict__ be, float* __restrict__ out) {
    int co = blockIdx.x, b = threadIdx.x;
    __shared__ float ws[128 * 16];
    for (int i = b; i < 128 * 16; i += 256)
        ws[i] = W[(i / 16) * 256 * 16 + co * 16 + (i % 16)];
    __syncthreads();
    float acc[31];
    float bv = bias[co];
    #pragma unroll
    for (int t = 0; t < 31; t++) acc[t] = bv;
    const float* xin = in + b * (128 * 16);
    for (int ci = 0; ci < 128; ci++) {
        float wr[16];
        #pragma unroll
        for (int kk = 0; kk < 16; kk++) wr[kk] = ws[ci * 16 + kk];
        const float* xr = xin + ci * 16;
        #pragma unroll
        for (int s2 = 0; s2 < 16; s2++) {
            float x = xr[s2];
            #pragma unroll
            for (int kk = 0; kk < 16; kk++) acc[s2 + kk] += x * wr[kk];
        }
    }
    float s = 0.f, ss = 0.f;
    #pragma unroll
    for (int t = 0; t < 31; t++) { s += acc[t]; ss += acc[t] * acc[t]; }
    reduce2_256(s, ss);
    const float invN = 1.f / (256.f * 31.f);
    float mean = s * invN, var = ss * invN - mean * mean;
    float sc = g[co] * rsqrtf(var + 1e-5f);
    float sh = be[co] - mean * sc;
    #pragma unroll
    for (int t = 0; t < 31; t++) {
        float v = acc[t] * sc + sh;
        out[(b * 256 + co) * 31 + t] = v >= 0.f ? v : 0.2f * v;
    }
}

// ---------------------------------------------------------------------------
// Stage 4: convT k=2 + tanh: (B,256,31) -> (B,512,32). W: (256, 512, 2).
// One block per co (512 blocks); thread = b.
// ---------------------------------------------------------------------------
__global__ void k_convT2(const float* __restrict__ in, const float* __restrict__ W,
                         const float* __restrict__ bias, float* __restrict__ out) {
    int co = blockIdx.x, b = threadIdx.x;
    __shared__ float ws[512];
    for (int i = b; i < 512; i += 256)
        ws[i] = W[(i / 2) * 512 * 2 + co * 2 + (i % 2)];
    __syncthreads();
    float acc[32];
    float bv = bias[co];
    #pragma unroll
    for (int t = 0; t < 32; t++) acc[t] = bv;
    const float* xin = in + b * (256 * 31);
    for (int ci = 0; ci < 256; ci++) {
        float w0 = ws[ci * 2], w1 = ws[ci * 2 + 1];
        const float* xr = xin + ci * 31;
        #pragma unroll
        for (int s2 = 0; s2 < 31; s2++) {
            float x = xr[s2];
            acc[s2]     += x * w0;
            acc[s2 + 1] += x * w1;
        }
    }
    #pragma unroll
    for (int t = 0; t < 32; t++)
        out[(b * 512 + co) * 32 + t] = tanhf(acc[t]);
}

// ---------------------------------------------------------------------------
// Stage 5: out[b,ch,y,x] = sum_r c[b,r,ch]*coef[r] * h[b,r,y] * w[b,r,x]
// One block per b; 1024 threads = (y,x). Stream r in chunks of 32 via SMEM.
// ---------------------------------------------------------------------------
__global__ void k_final(const float* __restrict__ coef, float* __restrict__ out) {
    int b = blockIdx.x, tid = threadIdx.x;
    int y = tid >> 5, x = tid & 31;
    __shared__ float shh[32 * 32], shw[32 * 32], shc[32 * 3];
    float a0 = 0.f, a1 = 0.f, a2 = 0.f;
    int ri = tid >> 5, rp = tid & 31;
    for (int r0 = 0; r0 < 512; r0 += 32) {
        shh[tid] = g_h3[(b * 512 + r0 + ri) * 32 + rp];
        shw[tid] = g_w3[(b * 512 + r0 + ri) * 32 + rp];
        if (tid < 96) {
            int rr = tid / 3, c3 = tid % 3;
            shc[tid] = g_c[(b * 512 + r0 + rr) * 3 + c3] * coef[r0 + rr];
        }
        __syncthreads();
        #pragma unroll
        for (int i = 0; i < 32; i++) {
            float p = shh[i * 32 + y] * shw[i * 32 + x];   // broadcast / conflict-free
            a0 += shc[i * 3 + 0] * p;
            a1 += shc[i * 3 + 1] * p;
            a2 += shc[i * 3 + 2] * p;
        }
        __syncthreads();
    }
    out[((b * 3 + 0) * 32 + y) * 32 + x] = a0;
    out[((b * 3 + 1) * 32 + y) * 32 + x] = a1;
    out[((b * 3 + 2) * 32 + y) * 32 + x] = a2;
}

// ---------------------------------------------------------------------------
extern "C" void kernel_launch(void* const* d_in, const int* in_sizes, int n_in,
                              void* d_out, int out_size) {
    const float* noise  = (const float*)d_in[0];
    const int*   label  = (const int*)  d_in[1];
    const float* lin_w  = (const float*)d_in[2];
    const float* lin_b  = (const float*)d_in[3];
    const float* bn0_g  = (const float*)d_in[4];
    const float* bn0_b  = (const float*)d_in[5];
    const float* emb    = (const float*)d_in[6];
    const float* c_w1   = (const float*)d_in[7];
    const float* c_b1   = (const float*)d_in[8];
    const float* c_g1   = (const float*)d_in[9];
    const float* c_be1  = (const float*)d_in[10];
    const float* h_w1   = (const float*)d_in[11];
    const float* h_b1   = (const float*)d_in[12];
    const float* h_g1   = (const float*)d_in[13];
    const float* h_be1  = (const float*)d_in[14];
    const float* h_w2   = (const float*)d_in[15];
    const float* h_b2   = (const float*)d_in[16];
    const float* h_g2   = (const float*)d_in[17];
    const float* h_be2  = (const float*)d_in[18];
    const float* h_w3   = (const float*)d_in[19];
    const float* h_b3   = (const float*)d_in[20];
    const float* w_w1   = (const float*)d_in[21];
    const float* w_b1   = (const float*)d_in[22];
    const float* w_g1   = (const float*)d_in[23];
    const float* w_be1  = (const float*)d_in[24];
    const float* w_w2   = (const float*)d_in[25];
    const float* w_b2   = (const float*)d_in[26];
    const float* w_g2   = (const float*)d_in[27];
    const float* w_be2  = (const float*)d_in[28];
    const float* w_w3   = (const float*)d_in[29];
    const float* w_b3   = (const float*)d_in[30];
    const float* coef   = (const float*)d_in[31];
    float* out = (float*)d_out;

    void *p_c, *p_h1, *p_w1, *p_h2, *p_w2, *p_h3, *p_w3;
    cudaGetSymbolAddress(&p_c,  g_c);
    cudaGetSymbolAddress(&p_h1, g_h1);
    cudaGetSymbolAddress(&p_w1, g_w1);
    cudaGetSymbolAddress(&p_h2, g_h2);
    cudaGetSymbolAddress(&p_w2, g_w2);
    cudaGetSymbolAddress(&p_h3, g_h3);
    cudaGetSymbolAddress(&p_w3, g_w3);

    k_latent<<<256, 256>>>(noise, label, lin_w, lin_b, bn0_g, bn0_b, emb);

    k_conv1<3> <<<512, 256, 256 * 3  * sizeof(float)>>>(c_w1, c_b1, c_g1, c_be1, (float*)p_c,  512, 0.2f);
    k_conv1<16><<<128, 256, 256 * 16 * sizeof(float)>>>(h_w1, h_b1, h_g1, h_be1, (float*)p_h1, 128, 0.2f);
    k_conv1<16><<<128, 256, 256 * 16 * sizeof(float)>>>(w_w1, w_b1, w_g1, w_be1, (float*)p_w1, 128, 0.2f);

    k_convT16<<<256, 256>>>((const float*)p_h1, h_w2, h_b2, h_g2, h_be2, (float*)p_h2);
    k_convT16<<<256, 256>>>((const float*)p_w1, w_w2, w_b2, w_g2, w_be2, (float*)p_w2);

    k_convT2<<<512, 256>>>((const float*)p_h2, h_w3, h_b3, (float*)p_h3);
    k_convT2<<<512, 256>>>((const float*)p_w2, w_w3, w_b3, (float*)p_w3);

    k_final<<<256, 1024>>>(coef, out);
}

// round 2
// speedup vs baseline: 14.7159x; 14.7159x over previous
#include <cuda_runtime.h>
#include <math.h>

// ---------------------------------------------------------------------------
// Constants: B=256, RANK=512, R4=128, R2=256
// Layouts:
//   g_latent : [ch][b]            (256 x 256)         channel-major (coalesced for conv1)
//   g_c      : [b][r][3]          post BN+lrelu
//   g_x1     : [s][b][ci][16]     post BN+lrelu (input to convT16), s=stack (0=h,1=w)
//   g_y2     : [s][b][co][32]     RAW conv2 output (+bias), slot t=31 is pad
//   g_psum/g_psq : [s][b][co]     per-(b,co) BN partials of y2
//   g_sc/g_sh    : [s][co]        BN scale/shift for layer-2 activations
//   g_o3     : [s][b][r][32]      tanh outputs of the two stacks
// ---------------------------------------------------------------------------

__device__ float g_latent[256 * 256];
__device__ float g_c[256 * 512 * 3];
__device__ float g_x1[2 * 256 * 128 * 16];
__device__ float g_y2[2 * 256 * 256 * 32];
__device__ float g_psum[2 * 256 * 256];
__device__ float g_psq [2 * 256 * 256];
__device__ float g_sc[2 * 256];
__device__ float g_sh[2 * 256];
__device__ float g_o3[2 * 256 * 512 * 32];

// Block-wide (256 threads) reduction of (sum, sumsq).
__device__ __forceinline__ void reduce2_256(float& s, float& ss) {
    __shared__ float rs[8], rss[8];
    #pragma unroll
    for (int o = 16; o > 0; o >>= 1) {
        s  += __shfl_down_sync(0xffffffffu, s,  o);
        ss += __shfl_down_sync(0xffffffffu, ss, o);
    }
    int wid = threadIdx.x >> 5, lane = threadIdx.x & 31;
    if (lane == 0) { rs[wid] = s; rss[wid] = ss; }
    __syncthreads();
    if (threadIdx.x < 32) {
        float a = lane < 8 ? rs[lane] : 0.f;
        float b = lane < 8 ? rss[lane] : 0.f;
        #pragma unroll
        for (int o = 4; o > 0; o >>= 1) {
            a += __shfl_down_sync(0xffffffffu, a, o);
            b += __shfl_down_sync(0xffffffffu, b, o);
        }
        if (lane == 0) { rs[0] = a; rss[0] = b; }
    }
    __syncthreads();
    s = rs[0]; ss = rss[0];
}

// ---------------------------------------------------------------------------
// Stage 1: z = lrelu(BN(noise @ lin_w.T + lin_b), 0.01); latent = [z ; emb[label]]
// blocks [0,128): z channel j (BN over batch); blocks [128,256): embedding row.
// Writes channel-major g_latent[ch][b].
// ---------------------------------------------------------------------------
__global__ void k_latent(const float* __restrict__ noise, const int* __restrict__ label,
                         const float* __restrict__ lin_w, const float* __restrict__ lin_b,
                         const float* __restrict__ g,     const float* __restrict__ be,
                         const float* __restrict__ emb) {
    int j = blockIdx.x, b = threadIdx.x;
    if (j >= 128) {
        int jj = j - 128;
        g_latent[(128 + jj) * 256 + b] = emb[label[b] * 128 + jj];
        return;
    }
    __shared__ float wsm[100];
    if (b < 100) wsm[b] = lin_w[j * 100 + b];
    __syncthreads();
    float acc = lin_b[j];
    const float* nb = noise + b * 100;
    #pragma unroll 4
    for (int i = 0; i < 100; i++) acc += nb[i] * wsm[i];
    float s = acc, ss = acc * acc;
    reduce2_256(s, ss);
    float mean = s * (1.f / 256.f);
    float var  = ss * (1.f / 256.f) - mean * mean;
    float sc   = g[j] * rsqrtf(var + 1e-5f);
    float v    = (acc - mean) * sc + be[j];
    g_latent[j * 256 + b] = v >= 0.f ? v : 0.01f * v;
}

// ---------------------------------------------------------------------------
// Stage 2a: c-branch conv1 (L=1 outer-product GEMM), K=3, Cout=512.
// block = co, thread = b. In-block BN over (b,t), lrelu 0.2. Writes g_c[b][r][3].
// ---------------------------------------------------------------------------
__global__ void k_conv1c(const float* __restrict__ W, const float* __restrict__ bias,
                         const float* __restrict__ g, const float* __restrict__ be) {
    int co = blockIdx.x, b = threadIdx.x;
    __shared__ float ws[256 * 3];
    for (int i = b; i < 256 * 3; i += 256)
        ws[i] = W[(i / 3) * 512 * 3 + co * 3 + (i % 3)];
    __syncthreads();
    float bv = bias[co];
    float a0 = bv, a1 = bv, a2 = bv;
    for (int ci = 0; ci < 256; ci++) {
        float x = g_latent[ci * 256 + b];
        a0 += x * ws[ci * 3 + 0];
        a1 += x * ws[ci * 3 + 1];
        a2 += x * ws[ci * 3 + 2];
    }
    float s = a0 + a1 + a2;
    float ss = a0 * a0 + a1 * a1 + a2 * a2;
    reduce2_256(s, ss);
    const float invN = 1.f / 768.f;
    float mean = s * invN, var = ss * invN - mean * mean;
    float sc = g[co] * rsqrtf(var + 1e-5f);
    float sh = be[co] - mean * sc;
    float v0 = a0 * sc + sh, v1 = a1 * sc + sh, v2 = a2 * sc + sh;
    float* o = g_c + (b * 512 + co) * 3;
    o[0] = v0 >= 0.f ? v0 : 0.2f * v0;
    o[1] = v1 >= 0.f ? v1 : 0.2f * v1;
    o[2] = v2 >= 0.f ? v2 : 0.2f * v2;
}

// ---------------------------------------------------------------------------
// Stage 2b: h/w-branch conv1, K=16, Cout=128, both stacks in one grid of 256.
// block: s = blockIdx.x>>7, co = blockIdx.x&127; thread = b.
// In-block BN over (b,t), lrelu 0.2. Writes g_x1[s][b][co][16].
// ---------------------------------------------------------------------------
__global__ void k_conv1hw(const float* __restrict__ hW, const float* __restrict__ hB,
                          const float* __restrict__ hG, const float* __restrict__ hBe,
                          const float* __restrict__ wW, const float* __restrict__ wB,
                          const float* __restrict__ wG, const float* __restrict__ wBe) {
    int s_ = blockIdx.x >> 7, co = blockIdx.x & 127, b = threadIdx.x;
    const float* W  = s_ ? wW  : hW;
    const float* Bi = s_ ? wB  : hB;
    const float* G  = s_ ? wG  : hG;
    const float* Be = s_ ? wBe : hBe;
    __shared__ float ws[256 * 16];
    for (int i = b; i < 256 * 16; i += 256)
        ws[i] = W[(i >> 4) * 128 * 16 + co * 16 + (i & 15)];
    __syncthreads();
    float acc[16];
    float bv = Bi[co];
    #pragma unroll
    for (int t = 0; t < 16; t++) acc[t] = bv;
    for (int ci = 0; ci < 256; ci++) {
        float x = g_latent[ci * 256 + b];
        #pragma unroll
        for (int t = 0; t < 16; t++) acc[t] += x * ws[ci * 16 + t];
    }
    float s = 0.f, ss = 0.f;
    #pragma unroll
    for (int t = 0; t < 16; t++) { s += acc[t]; ss += acc[t] * acc[t]; }
    reduce2_256(s, ss);
    const float invN = 1.f / (256.f * 16.f);
    float mean = s * invN, var = ss * invN - mean * mean;
    float sc = G[co] * rsqrtf(var + 1e-5f);
    float sh = Be[co] - mean * sc;
    float* o = g_x1 + s_ * (256 * 128 * 16) + (b * 128 + co) * 16;
    #pragma unroll
    for (int t = 0; t < 16; t++) {
        float v = acc[t] * sc + sh;
        o[t] = v >= 0.f ? v : 0.2f * v;
    }
}

// ---------------------------------------------------------------------------
// Stage 3: convT k=16: (B,128,16) -> (B,256,31). RAW output + BN partials.
// grid 512: s = blockIdx.x>>8, b = blockIdx.x&255; thread = co (256).
// X (8KB) staged in smem (coalesced); W streamed from L2 (contiguous in co,k).
// ---------------------------------------------------------------------------
__global__ void __launch_bounds__(256)
k_convT16(const float* __restrict__ hW, const float* __restrict__ hB,
          const float* __restrict__ wW, const float* __restrict__ wB) {
    int s_ = blockIdx.x >> 8, b = blockIdx.x & 255, co = threadIdx.x;
    __shared__ float X[128 * 16];
    const float* xin = g_x1 + s_ * (256 * 128 * 16) + b * 2048;
    for (int i = co; i < 2048; i += 256) X[i] = xin[i];
    __syncthreads();

    const float* W  = (s_ ? wW : hW) + co * 16;
    const float* Bi = s_ ? wB : hB;
    float acc[31];
    float bv = Bi[co];
    #pragma unroll
    for (int t = 0; t < 31; t++) acc[t] = bv;

    for (int ci = 0; ci < 128; ci++) {
        const float4* wp = (const float4*)(W + ci * 4096);
        float4 wa = wp[0], wb = wp[1], wc = wp[2], wd = wp[3];
        float wr[16] = {wa.x, wa.y, wa.z, wa.w, wb.x, wb.y, wb.z, wb.w,
                        wc.x, wc.y, wc.z, wc.w, wd.x, wd.y, wd.z, wd.w};
        const float* xr = X + ci * 16;
        #pragma unroll
        for (int s2 = 0; s2 < 16; s2++) {
            float x = xr[s2];                 // smem broadcast
            #pragma unroll
            for (int k = 0; k < 16; k++) acc[s2 + k] += x * wr[k];
        }
    }
    float sum = 0.f, sq = 0.f;
    #pragma unroll
    for (int t = 0; t < 31; t++) { sum += acc[t]; sq += acc[t] * acc[t]; }

    float* o = g_y2 + s_ * (256 * 256 * 32) + (b * 256 + co) * 32;
    #pragma unroll
    for (int t = 0; t < 31; t++) o[t] = acc[t];
    o[31] = 0.f;
    g_psum[s_ * 65536 + b * 256 + co] = sum;
    g_psq [s_ * 65536 + b * 256 + co] = sq;
}

// ---------------------------------------------------------------------------
// Stage 3b: reduce BN partials -> per-channel scale/shift. grid 2 x 256.
// ---------------------------------------------------------------------------
__global__ void k_bnstat(const float* __restrict__ hG, const float* __restrict__ hBe,
                         const float* __restrict__ wG, const float* __restrict__ wBe) {
    int s_ = blockIdx.x, co = threadIdx.x;
    const float* G  = s_ ? wG  : hG;
    const float* Be = s_ ? wBe : hBe;
    float sum = 0.f, sq = 0.f;
    for (int b = 0; b < 256; b++) {
        sum += g_psum[s_ * 65536 + b * 256 + co];
        sq  += g_psq [s_ * 65536 + b * 256 + co];
    }
    const float invN = 1.f / (256.f * 31.f);
    float mean = sum * invN, var = sq * invN - mean * mean;
    float sc = G[co] * rsqrtf(var + 1e-5f);
    g_sc[s_ * 256 + co] = sc;
    g_sh[s_ * 256 + co] = Be[co] - mean * sc;
}

// ---------------------------------------------------------------------------
// Stage 4: convT k=2 + tanh: (B,256,31) -> (B,512,32).
// grid 512: s = blockIdx.x>>8, b = blockIdx.x&255; 512 threads = co.
// BN+lrelu applied to X while staging into smem. W3 read as float2 (coalesced).
// ---------------------------------------------------------------------------
__global__ void __launch_bounds__(512)
k_convT2(const float* __restrict__ hW, const float* __restrict__ hB,
         const float* __restrict__ wW, const float* __restrict__ wB) {
    int s_ = blockIdx.x >> 8, b = blockIdx.x & 255, co = threadIdx.x;
    __shared__ float scs[256], shs[256];
    __shared__ float X[256 * 32];
    if (co < 256) { scs[co] = g_sc[s_ * 256 + co]; shs[co] = g_sh[s_ * 256 + co]; }
    __syncthreads();
    const float4* in4 = (const float4*)(g_y2 + s_ * (256 * 256 * 32) + b * 8192);
    for (int i = co; i < 2048; i += 512) {
        float4 v = in4[i];
        int ci = i >> 3;
        float sc = scs[ci], sh = shs[ci];
        float x0 = v.x * sc + sh; x0 = x0 >= 0.f ? x0 : 0.2f * x0;
        float x1 = v.y * sc + sh; x1 = x1 >= 0.f ? x1 : 0.2f * x1;
        float x2 = v.z * sc + sh; x2 = x2 >= 0.f ? x2 : 0.2f * x2;
        float x3 = v.w * sc + sh; x3 = x3 >= 0.f ? x3 : 0.2f * x3;
        if ((i & 7) == 7) x3 = 0.f;          // t == 31 pad
        float4 o; o.x = x0; o.y = x1; o.z = x2; o.w = x3;
        ((float4*)X)[i] = o;
    }
    __syncthreads();

    const float* W  = s_ ? wW : hW;
    const float* Bi = s_ ? wB : hB;
    float acc[32];
    float bv = Bi[co];
    #pragma unroll
    for (int t = 0; t < 32; t++) acc[t] = bv;

    for (int ci = 0; ci < 256; ci++) {
        float2 w = ((const float2*)(W + ci * 1024))[co];
        const float* xr = X + ci * 32;
        float xp = xr[0];
        acc[0] += xp * w.x;
        #pragma unroll
        for (int t = 1; t < 32; t++) {
            float xc = xr[t];                // xr[31] == 0 (pad)
            acc[t] += xc * w.x + xp * w.y;
            xp = xc;
        }
    }
    float* o = g_o3 + s_ * (256 * 512 * 32) + (b * 512 + co) * 32;
    #pragma unroll
    for (int t = 0; t < 32; t++) o[t] = tanhf(acc[t]);
}

// ---------------------------------------------------------------------------
// Stage 5: out[b,ch,y,x] = sum_r c[b,r,ch]*coef[r] * h[b,r,y] * w[b,r,x]
// ---------------------------------------------------------------------------
__global__ void k_final(const float* __restrict__ coef, float* __restrict__ out) {
    int b = blockIdx.x, tid = threadIdx.x;
    int y = tid >> 5, x = tid & 31;
    __shared__ float shh[32 * 32], shw[32 * 32], shc[32 * 3];
    float a0 = 0.f, a1 = 0.f, a2 = 0.f;
    int ri = tid >> 5, rp = tid & 31;
    for (int r0 = 0; r0 < 512; r0 += 32) {
        shh[tid] = g_o3[                 (b * 512 + r0 + ri) * 32 + rp];
        shw[tid] = g_o3[256 * 512 * 32 + (b * 512 + r0 + ri) * 32 + rp];
        if (tid < 96) {
            int rr = tid / 3, c3 = tid % 3;
            shc[tid] = g_c[(b * 512 + r0 + rr) * 3 + c3] * coef[r0 + rr];
        }
        __syncthreads();
        #pragma unroll
        for (int i = 0; i < 32; i++) {
            float p = shh[i * 32 + y] * shw[i * 32 + x];
            a0 += shc[i * 3 + 0] * p;
            a1 += shc[i * 3 + 1] * p;
            a2 += shc[i * 3 + 2] * p;
        }
        __syncthreads();
    }
    out[((b * 3 + 0) * 32 + y) * 32 + x] = a0;
    out[((b * 3 + 1) * 32 + y) * 32 + x] = a1;
    out[((b * 3 + 2) * 32 + y) * 32 + x] = a2;
}

// ---------------------------------------------------------------------------
extern "C" void kernel_launch(void* const* d_in, const int* in_sizes, int n_in,
                              void* d_out, int out_size) {
    const float* noise  = (const float*)d_in[0];
    const int*   label  = (const int*)  d_in[1];
    const float* lin_w  = (const float*)d_in[2];
    const float* lin_b  = (const float*)d_in[3];
    const float* bn0_g  = (const float*)d_in[4];
    const float* bn0_b  = (const float*)d_in[5];
    const float* emb    = (const float*)d_in[6];
    const float* c_w1   = (const float*)d_in[7];
    const float* c_b1   = (const float*)d_in[8];
    const float* c_g1   = (const float*)d_in[9];
    const float* c_be1  = (const float*)d_in[10];
    const float* h_w1   = (const float*)d_in[11];
    const float* h_b1   = (const float*)d_in[12];
    const float* h_g1   = (const float*)d_in[13];
    const float* h_be1  = (const float*)d_in[14];
    const float* h_w2   = (const float*)d_in[15];
    const float* h_b2   = (const float*)d_in[16];
    const float* h_g2   = (const float*)d_in[17];
    const float* h_be2  = (const float*)d_in[18];
    const float* h_w3   = (const float*)d_in[19];
    const float* h_b3   = (const float*)d_in[20];
    const float* w_w1   = (const float*)d_in[21];
    const float* w_b1   = (const float*)d_in[22];
    const float* w_g1   = (const float*)d_in[23];
    const float* w_be1  = (const float*)d_in[24];
    const float* w_w2   = (const float*)d_in[25];
    const float* w_b2   = (const float*)d_in[26];
    const float* w_g2   = (const float*)d_in[27];
    const float* w_be2  = (const float*)d_in[28];
    const float* w_w3   = (const float*)d_in[29];
    const float* w_b3   = (const float*)d_in[30];
    const float* coef   = (const float*)d_in[31];
    float* out = (float*)d_out;

    k_latent <<<256, 256>>>(noise, label, lin_w, lin_b, bn0_g, bn0_b, emb);
    k_conv1c <<<512, 256>>>(c_w1, c_b1, c_g1, c_be1);
    k_conv1hw<<<256, 256>>>(h_w1, h_b1, h_g1, h_be1, w_w1, w_b1, w_g1, w_be1);
    k_convT16<<<512, 256>>>(h_w2, h_b2, w_w2, w_b2);
    k_bnstat <<<2,   256>>>(h_g2, h_be2, w_g2, w_be2);
    k_convT2 <<<512, 512>>>(h_w3, h_b3, w_w3, w_b3);
    k_final  <<<256, 1024>>>(coef, out);
}